// round 10
// baseline (speedup 1.0000x reference)
#include <cuda_runtime.h>
#include <cstdint>

// DCTExtractor: gray = 0.299R+0.587G+0.114B, per-8x8-block 2D DCT
// (D @ blk @ D^T) * mask -> (B,1,H,W).
//
// cp.async.bulk double-buffered smem pipeline. Tile = one block-row of one
// image: 3 contiguous 16KB channel slices bulk-copied into smem, then the
// proven one-thread-per-block register DCT computes from smem. Bytes in
// flight no longer consume registers -> latency fully hidden. Persistent
// CTAs (2/SM, smem-limited), 64 threads each.

#define TPB 64
#define NBUF 2
#define CH_BYTES 16384                 // 8 rows * 512 cols * 4B
#define TILE_BYTES (3 * CH_BYTES)      // 49152
#define TILE_FLOATS (3 * 4096)

__device__ __forceinline__ uint32_t smem_u32(const void* p) {
    uint32_t a;
    asm("{ .reg .u64 t; cvta.to.shared.u64 t, %1; cvt.u32.u64 %0, t; }"
        : "=r"(a) : "l"(p));
    return a;
}

__device__ __forceinline__ void mbar_init(uint32_t addr, uint32_t cnt) {
    asm volatile("mbarrier.init.shared.b64 [%0], %1;" :: "r"(addr), "r"(cnt) : "memory");
}
__device__ __forceinline__ void mbar_expect_tx(uint32_t addr, uint32_t bytes) {
    asm volatile("mbarrier.arrive.expect_tx.shared.b64 _, [%0], %1;"
                 :: "r"(addr), "r"(bytes) : "memory");
}
__device__ __forceinline__ void mbar_wait(uint32_t addr, uint32_t parity) {
    uint32_t done;
    asm volatile(
        "{\n\t.reg .pred p;\n\t"
        "mbarrier.try_wait.parity.acquire.cta.shared::cta.b64 p, [%1], %2;\n\t"
        "selp.b32 %0, 1, 0, p;\n\t}"
        : "=r"(done) : "r"(addr), "r"(parity) : "memory");
    if (!done) {
        asm volatile(
            "{\n\t.reg .pred P1;\n\t"
            "WL_%=:\n\t"
            "mbarrier.try_wait.parity.acquire.cta.shared::cta.b64 P1, [%0], %1, 0x989680;\n\t"
            "@P1 bra.uni WD_%=;\n\t"
            "bra.uni WL_%=;\n\t"
            "WD_%=:\n\t}"
            :: "r"(addr), "r"(parity) : "memory");
    }
}
__device__ __forceinline__ void bulk_cp(uint32_t dst_smem, const void* src, uint32_t bytes,
                                        uint32_t mbar) {
    asm volatile(
        "cp.async.bulk.shared::cta.global.mbarrier::complete_tx::bytes [%0], [%1], %2, [%3];"
        :: "r"(dst_smem), "l"(src), "r"(bytes), "r"(mbar) : "memory");
}

__global__ void __launch_bounds__(TPB)
dct_extract_kernel(const float* __restrict__ x,
                   const float* __restrict__ dctm,
                   const float* __restrict__ mask,
                   float* __restrict__ out,
                   int ntiles)
{
    extern __shared__ __align__(16) float buf[];     // NBUF * TILE_FLOATS
    __shared__ float Ds[64];
    __shared__ float Ms[64];
    __shared__ __align__(8) unsigned long long mbar_store[NBUF];

    const int t = threadIdx.x;
    Ds[t] = dctm[t];
    Ms[t] = mask[t];

    const uint32_t mb0 = smem_u32(&mbar_store[0]);
    const uint32_t mb1 = smem_u32(&mbar_store[1]);
    if (t == 0) { mbar_init(mb0, 1); mbar_init(mb1, 1); }
    __syncthreads();

    const int W  = 512;
    const int HW = 512 * 512;
    const int gsz = gridDim.x;

    // number of tiles this CTA owns: indices blockIdx.x + i*gsz < ntiles
    const int nmine = (ntiles - blockIdx.x + gsz - 1) / gsz;

    const uint32_t buf0 = smem_u32(buf);

    // ---- prologue: prefetch up to NBUF tiles ----
    if (t == 0) {
#pragma unroll
        for (int s = 0; s < NBUF; ++s) {
            if (s < nmine) {
                const int T = blockIdx.x + s * gsz;
                const int b = T >> 6, by = T & 63;
                const float* src = x + (size_t)b * 3 * HW + (size_t)(by * 8) * W;
                const uint32_t mb = s ? mb1 : mb0;
                mbar_expect_tx(mb, TILE_BYTES);
                const uint32_t d = buf0 + s * TILE_BYTES;
                bulk_cp(d,                src,            CH_BYTES, mb);
                bulk_cp(d + CH_BYTES,     src + HW,       CH_BYTES, mb);
                bulk_cp(d + 2 * CH_BYTES, src + 2 * HW,   CH_BYTES, mb);
            }
        }
    }

    for (int i = 0; i < nmine; ++i) {
        const int s = i & 1;
        const uint32_t mb = s ? mb1 : mb0;
        mbar_wait(mb, (i >> 1) & 1);

        const int T  = blockIdx.x + i * gsz;
        const int b  = T >> 6, by = T & 63;

        const float* bR = buf + s * TILE_FLOATS;
        const float* bG = bR + 4096;
        const float* bB = bG + 4096;
        const int off = t * 8;   // my block's column offset within the row

        // ---- fused grayscale load from smem (LDS.128) ----
        float g[8][8];
#pragma unroll
        for (int j = 0; j < 8; ++j) {
            const int ro = j * 512 + off;
            const float4 r0 = *(const float4*)(bR + ro);
            const float4 r1 = *(const float4*)(bR + ro + 4);
            const float4 g0 = *(const float4*)(bG + ro);
            const float4 g1 = *(const float4*)(bG + ro + 4);
            const float4 b0 = *(const float4*)(bB + ro);
            const float4 b1 = *(const float4*)(bB + ro + 4);
            g[j][0] = fmaf(0.114f, b0.x, fmaf(0.587f, g0.x, 0.299f * r0.x));
            g[j][1] = fmaf(0.114f, b0.y, fmaf(0.587f, g0.y, 0.299f * r0.y));
            g[j][2] = fmaf(0.114f, b0.z, fmaf(0.587f, g0.z, 0.299f * r0.z));
            g[j][3] = fmaf(0.114f, b0.w, fmaf(0.587f, g0.w, 0.299f * r0.w));
            g[j][4] = fmaf(0.114f, b1.x, fmaf(0.587f, g1.x, 0.299f * r1.x));
            g[j][5] = fmaf(0.114f, b1.y, fmaf(0.587f, g1.y, 0.299f * r1.y));
            g[j][6] = fmaf(0.114f, b1.z, fmaf(0.587f, g1.z, 0.299f * r1.z));
            g[j][7] = fmaf(0.114f, b1.w, fmaf(0.587f, g1.w, 0.299f * r1.w));
        }

        // ---- separable DCT + mask, write out (coalesced STG.128) ----
        float* po = out + (size_t)b * HW + (size_t)(by * 8) * W + off;
#pragma unroll
        for (int ii = 0; ii < 8; ++ii) {
            float tr[8];
#pragma unroll
            for (int k = 0; k < 8; ++k) {
                float sacc = Ds[ii * 8 + 0] * g[0][k];
#pragma unroll
                for (int j = 1; j < 8; ++j)
                    sacc = fmaf(Ds[ii * 8 + j], g[j][k], sacc);
                tr[k] = sacc;
            }
            float o[8];
#pragma unroll
            for (int l = 0; l < 8; ++l) {
                float sacc = tr[0] * Ds[l * 8 + 0];
#pragma unroll
                for (int k = 1; k < 8; ++k)
                    sacc = fmaf(tr[k], Ds[l * 8 + k], sacc);
                o[l] = sacc * Ms[ii * 8 + l];
            }
            float* row = po + ii * W;
            *(float4*)(row)     = make_float4(o[0], o[1], o[2], o[3]);
            *(float4*)(row + 4) = make_float4(o[4], o[5], o[6], o[7]);
        }

        __syncthreads();   // all threads done reading buf[s]

        // ---- refill buf[s] with tile i+NBUF ----
        const int nx = i + NBUF;
        if (t == 0 && nx < nmine) {
            const int Tn = blockIdx.x + nx * gsz;
            const int bn = Tn >> 6, byn = Tn & 63;
            const float* src = x + (size_t)bn * 3 * HW + (size_t)(byn * 8) * W;
            mbar_expect_tx(mb, TILE_BYTES);
            const uint32_t d = buf0 + s * TILE_BYTES;
            bulk_cp(d,                src,          CH_BYTES, mb);
            bulk_cp(d + CH_BYTES,     src + HW,     CH_BYTES, mb);
            bulk_cp(d + 2 * CH_BYTES, src + 2 * HW, CH_BYTES, mb);
        }
    }
}

extern "C" void kernel_launch(void* const* d_in, const int* in_sizes, int n_in,
                              void* d_out, int out_size)
{
    const float* x    = (const float*)d_in[0];
    const float* dctm = (const float*)d_in[1];
    const float* mask = (const float*)d_in[2];
    float* out        = (float*)d_out;

    const int HW = 512 * 512;
    const int B  = in_sizes[0] / (3 * HW);   // 64
    const int ntiles = B * 64;               // 4096 block-rows (tiles)

    const int dyn_smem = NBUF * TILE_BYTES;  // 98304 B
    cudaFuncSetAttribute(dct_extract_kernel,
                         cudaFuncAttributeMaxDynamicSharedMemorySize, dyn_smem);

    int dev = 0, num_sms = 148;
    cudaGetDevice(&dev);
    cudaDeviceGetAttribute(&num_sms, cudaDevAttrMultiProcessorCount, dev);

    const int grid = 2 * num_sms;            // 2 CTAs/SM (smem-limited)
    dct_extract_kernel<<<grid, TPB, dyn_smem>>>(x, dctm, mask, out, ntiles);
}

// round 11
// speedup vs baseline: 1.0801x; 1.0801x over previous
#include <cuda_runtime.h>
#include <cuda_bf16.h>

// DCTExtractor: gray = 0.299R + 0.587G + 0.114B, per-8x8-block 2D DCT
// (D @ blk @ D^T) * mask, folded back to (B,1,H,W).
//
// R8 structure (best measured: one thread per 8x8 block, register-resident,
// TPB=64, 4096 CTAs) with ONE change: evict-first streaming cache hints
// (__ldcs/__stcs) on all global traffic. Zero-reuse 242MB stream through a
// 126MB L2 -> stop paying for retention. Single-variable experiment vs R8.

#define TPB 64

__global__ __launch_bounds__(TPB, 8)
void dct_extract_kernel(const float* __restrict__ x,
                        const float* __restrict__ dctm,
                        const float* __restrict__ mask,
                        float* __restrict__ out,
                        int total)
{
    __shared__ float Ds[64];
    __shared__ float Ms[64];
    const int t = threadIdx.x;
    Ds[t] = dctm[t];
    Ms[t] = mask[t];
    __syncthreads();

    const int gid = blockIdx.x * TPB + t;
    if (gid >= total) return;

    const int W  = 512;
    const int HW = 512 * 512;

    // gid -> (batch, block_y, block_x); nh = nw = 64 -> 4096 blocks/image
    const int b  = gid >> 12;
    const int rr = gid & 4095;
    const int by = rr >> 6;
    const int bx = rr & 63;

    const float* p0 = x + (size_t)b * 3 * HW + (size_t)(by * 8) * W + bx * 8;

    // ---- load 8x8 grayscale block into registers (LDG.128, evict-first) ----
    float g[8][8];
#pragma unroll
    for (int j = 0; j < 8; ++j) {
        const float* row = p0 + j * W;
        const float4 r0 = __ldcs((const float4*)(row));
        const float4 r1 = __ldcs((const float4*)(row + 4));
        const float4 g0 = __ldcs((const float4*)(row + HW));
        const float4 g1 = __ldcs((const float4*)(row + HW + 4));
        const float4 b0 = __ldcs((const float4*)(row + 2 * HW));
        const float4 b1 = __ldcs((const float4*)(row + 2 * HW + 4));
        g[j][0] = fmaf(0.114f, b0.x, fmaf(0.587f, g0.x, 0.299f * r0.x));
        g[j][1] = fmaf(0.114f, b0.y, fmaf(0.587f, g0.y, 0.299f * r0.y));
        g[j][2] = fmaf(0.114f, b0.z, fmaf(0.587f, g0.z, 0.299f * r0.z));
        g[j][3] = fmaf(0.114f, b0.w, fmaf(0.587f, g0.w, 0.299f * r0.w));
        g[j][4] = fmaf(0.114f, b1.x, fmaf(0.587f, g1.x, 0.299f * r1.x));
        g[j][5] = fmaf(0.114f, b1.y, fmaf(0.587f, g1.y, 0.299f * r1.y));
        g[j][6] = fmaf(0.114f, b1.z, fmaf(0.587f, g1.z, 0.299f * r1.z));
        g[j][7] = fmaf(0.114f, b1.w, fmaf(0.587f, g1.w, 0.299f * r1.w));
    }

    // ---- separable DCT, one output row at a time: out[i][:] = (D[i,:] @ g) @ D^T ----
    float* po = out + (size_t)b * HW + (size_t)(by * 8) * W + bx * 8;

#pragma unroll
    for (int i = 0; i < 8; ++i) {
        // temp row: tr[k] = sum_j D[i][j] * g[j][k]
        float tr[8];
#pragma unroll
        for (int k = 0; k < 8; ++k) {
            float s = Ds[i * 8 + 0] * g[0][k];
#pragma unroll
            for (int j = 1; j < 8; ++j)
                s = fmaf(Ds[i * 8 + j], g[j][k], s);
            tr[k] = s;
        }
        // out row: o[l] = (sum_k tr[k] * D[l][k]) * mask[i][l]
        float o[8];
#pragma unroll
        for (int l = 0; l < 8; ++l) {
            float s = tr[0] * Ds[l * 8 + 0];
#pragma unroll
            for (int k = 1; k < 8; ++k)
                s = fmaf(tr[k], Ds[l * 8 + k], s);
            o[l] = s * Ms[i * 8 + l];
        }
        float* row = po + i * W;
        __stcs((float4*)(row),     make_float4(o[0], o[1], o[2], o[3]));
        __stcs((float4*)(row + 4), make_float4(o[4], o[5], o[6], o[7]));
    }
}

extern "C" void kernel_launch(void* const* d_in, const int* in_sizes, int n_in,
                              void* d_out, int out_size)
{
    const float* x    = (const float*)d_in[0];
    const float* dctm = (const float*)d_in[1];
    const float* mask = (const float*)d_in[2];
    float* out        = (float*)d_out;

    const int HW = 512 * 512;
    const int B  = in_sizes[0] / (3 * HW);      // 64
    const int total = B * 64 * 64;              // one thread per 8x8 block

    const int grid = (total + TPB - 1) / TPB;   // 4096; one block-row per CTA
    dct_extract_kernel<<<grid, TPB>>>(x, dctm, mask, out, total);
}